// round 11
// baseline (speedup 1.0000x reference)
#include <cuda_runtime.h>
#include <cuda_bf16.h>

#define NN 4096
#define BB 2
#define CC 64
#define MSPLIT 2

typedef unsigned int u32;

// Scratch
__device__ __nv_bfloat16 g_qh[(size_t)BB * NN * 8];           // [b][n][8c] (q pre-scaled by log2e)
__device__ __nv_bfloat16 g_kh[(size_t)BB * NN * 8];           // [b][m][8c]
__device__ __nv_bfloat16 g_vh[(size_t)BB * CC * NN];          // [b][c][m]
__device__ __nv_bfloat16 g_po[(size_t)MSPLIT * BB * CC * NN]; // partial O [s][b][c][n]
__device__ float g_prs[(size_t)MSPLIT * BB * NN];             // partial rowsum [s][b][n]
__device__ int g_tk[BB * 64];                                 // tickets (mod-MSPLIT)

// Per-group stage: K slice 512B (32 rows x 16B) + V slice (64 c-rows x 80B, 64B data)
#define STG_K 512
#define STG_SZ 5632            // 512 + 64*80
#define GRP_SZ (4 * STG_SZ)    // 4-stage ring per group

__device__ __forceinline__ u32 packbf(float lo, float hi) {
    u32 r;
    asm("cvt.rn.bf16x2.f32 %0, %1, %2;" : "=r"(r) : "f"(hi), "f"(lo));
    return r;
}
__device__ __forceinline__ float2 unpackbf(u32 v) {
    __nv_bfloat162 h = *(__nv_bfloat162*)&v;
    return make_float2(__bfloat162float(h.x), __bfloat162float(h.y));
}
__device__ __forceinline__ float ex2(float x) {
    float y;
    asm("ex2.approx.ftz.f32 %0, %1;" : "=f"(y) : "f"(x));
    return y;
}

__device__ __forceinline__ void mma_bf16_k8(float d[4], u32 a0, u32 a1, u32 b0) {
    asm("mma.sync.aligned.m16n8k8.row.col.f32.bf16.bf16.f32 "
        "{%0,%1,%2,%3}, {%4,%5}, {%6}, {%0,%1,%2,%3};"
        : "+f"(d[0]), "+f"(d[1]), "+f"(d[2]), "+f"(d[3])
        : "r"(a0), "r"(a1), "r"(b0));
}
__device__ __forceinline__ void mma_bf16_k16(float d[4], u32 a0, u32 a1, u32 a2, u32 a3,
                                             u32 b0, u32 b1) {
    asm("mma.sync.aligned.m16n8k16.row.col.f32.bf16.bf16.f32 "
        "{%0,%1,%2,%3}, {%4,%5,%6,%7}, {%8,%9}, {%0,%1,%2,%3};"
        : "+f"(d[0]), "+f"(d[1]), "+f"(d[2]), "+f"(d[3])
        : "r"(a0), "r"(a1), "r"(a2), "r"(a3), "r"(b0), "r"(b1));
}
__device__ __forceinline__ void ldsm_x4(u32& r0, u32& r1, u32& r2, u32& r3, u32 saddr) {
    asm volatile("ldmatrix.sync.aligned.m8n8.x4.shared.b16 {%0,%1,%2,%3}, [%4];"
                 : "=r"(r0), "=r"(r1), "=r"(r2), "=r"(r3) : "r"(saddr));
}
__device__ __forceinline__ void cp16(u32 dst, const void* src) {
    asm volatile("cp.async.cg.shared.global [%0], [%1], 16;" :: "r"(dst), "l"(src));
}
__device__ __forceinline__ void cp4(u32 dst, const void* src) {
    asm volatile("cp.async.ca.shared.global [%0], [%1], 4;" :: "r"(dst), "l"(src));
}
__device__ __forceinline__ void cp_commit() { asm volatile("cp.async.commit_group;"); }
__device__ __forceinline__ void cp_wait0() { asm volatile("cp.async.wait_group 0;"); }
__device__ __forceinline__ void cp_wait2() { asm volatile("cp.async.wait_group 2;"); }
__device__ __forceinline__ void gbar(int id) {
    asm volatile("bar.sync %0, 128;" :: "r"(id) : "memory");
}

// ---------------------------------------------------------------------------
// Fused projection kernel, ONE launch, 512 CTAs. (unchanged)
// ---------------------------------------------------------------------------
__global__ __launch_bounds__(256) void proj_kernel(const float* __restrict__ x,
                                                   const float* __restrict__ ctx,
                                                   const float* __restrict__ Wq,
                                                   const float* __restrict__ bq,
                                                   const float* __restrict__ Wk,
                                                   const float* __restrict__ bk,
                                                   const float* __restrict__ Wv,
                                                   const float* __restrict__ bv) {
    const int tid = threadIdx.x;
    const int role = blockIdx.x >> 8;
    const int idx = blockIdx.x & 255;
    const int b = idx >> 7;
    const int n0 = (idx & 127) * 32;
    const float LOG2E = 1.4426950408889634f;

    if (role == 0) {
        __shared__ float sx[64][36];
        __shared__ float sct[64][36];
        __shared__ float sW[16][64];
        __shared__ float sb[16];

        for (int i = tid; i < 512; i += 256) {
            sW[i >> 6][i & 63] = Wq[i] * LOG2E;
            sW[8 + (i >> 6)][i & 63] = Wk[i];
        }
        if (tid < 8) { sb[tid] = bq[tid] * LOG2E; sb[8 + tid] = bk[tid]; }
#pragma unroll
        for (int k = 0; k < 2; k++) {
            int i = k * 256 + tid;
            int r = i >> 3, f4 = (i & 7) * 4;
            *(float4*)&sx[r][f4] = *(const float4*)&x[((size_t)b * CC + r) * NN + n0 + f4];
            *(float4*)&sct[r][f4] = *(const float4*)&ctx[((size_t)b * CC + r) * NN + n0 + f4];
        }
        __syncthreads();

        const int n = tid & 31;
        const int og = tid >> 5;
        const bool isk = og >= 4;
        const int r2 = 2 * (og & 3);
        const int wrow = (isk ? 8 : 0) + r2;
        float a0 = sb[wrow], a1 = sb[wrow + 1];
#pragma unroll
        for (int c = 0; c < 64; c++) {
            float v = isk ? sct[c][n] : sx[c][n];
            a0 = fmaf(sW[wrow][c], v, a0);
            a1 = fmaf(sW[wrow + 1][c], v, a1);
        }
        __nv_bfloat16* dst = isk ? g_kh : g_qh;
        *(u32*)(dst + ((size_t)b * NN + n0 + n) * 8 + r2) = packbf(a0, a1);
    } else {
        __shared__ float sC[64][36];
        __shared__ float sWv[64][68];
        __shared__ float sbv[64];

        for (int i = tid; i < 4096; i += 256) sWv[i & 63][i >> 6] = Wv[i];
        if (tid < 64) sbv[tid] = bv[tid];
#pragma unroll
        for (int k = 0; k < 2; k++) {
            int i = k * 256 + tid;
            int r = i >> 3, f4 = (i & 7) * 4;
            *(float4*)&sC[r][f4] = *(const float4*)&ctx[((size_t)b * CC + r) * NN + n0 + f4];
        }
        __syncthreads();

        const int m2 = (tid & 15) * 2;
        const int cg = (tid >> 4) * 4;
        float acc[4][2];
#pragma unroll
        for (int j = 0; j < 4; j++) acc[j][0] = acc[j][1] = sbv[cg + j];
#pragma unroll
        for (int cc = 0; cc < 64; cc++) {
            float2 vm = *(const float2*)&sC[cc][m2];
            float4 wv = *(const float4*)&sWv[cc][cg];
            float ww[4] = {wv.x, wv.y, wv.z, wv.w};
#pragma unroll
            for (int j = 0; j < 4; j++) {
                acc[j][0] = fmaf(ww[j], vm.x, acc[j][0]);
                acc[j][1] = fmaf(ww[j], vm.y, acc[j][1]);
            }
        }
#pragma unroll
        for (int j = 0; j < 4; j++)
            *(u32*)(g_vh + ((size_t)b * CC + cg + j) * NN + n0 + m2) = packbf(acc[j][0], acc[j][1]);
    }
}

// ---------------------------------------------------------------------------
// Attention: per-h-group smem rings + named barriers -> groups free-run in
// counter-phase. No CTA-wide barrier in the mainloop.
//   grid (64 qtiles, B, 2), 256 threads = 8 warps (2 groups of 4), 2 CTAs/SM.
// ---------------------------------------------------------------------------
__global__ __launch_bounds__(256, 2) void attn_kernel(const float* __restrict__ x,
                                                      const float* __restrict__ gammap,
                                                      float* __restrict__ out) {
    __shared__ __nv_bfloat16 sQ[64][8];
    __shared__ __align__(16) char svbuf[2 * GRP_SZ];   // 2 group rings / sO alias
    __shared__ float sRS[64][2];
    __shared__ float sInv[64];
    __shared__ int sFlag;
    float (*sO)[65] = (float (*)[65])svbuf;

    const int tid = threadIdx.x;
    const int b = blockIdx.y;
    const int q0 = blockIdx.x * 64;
    const int s = blockIdx.z;
    const int ck0 = s * 32;
    const int w = tid >> 5;
    const int lane = tid & 31;
    const int g = lane >> 2;
    const int t = lane & 3;
    const int qT = w & 3;
    const int h = w >> 2;
    const int r = 16 * qT + g;
    const int gt = tid & 127;        // group-local thread id

    const char* gk = (const char*)g_kh + (size_t)b * NN * 8 * 2;
    const char* gv = (const char*)g_vh + (size_t)b * CC * NN * 2;

    ((u32*)sQ)[tid] = ((const u32*)((const char*)g_qh + ((size_t)b * NN + q0) * 16))[tid];

    // Group ring base (shared-space)
    const u32 svb = (u32)__cvta_generic_to_shared(svbuf);
    const u32 gb = svb + h * GRP_SZ;
    // ldmatrix addresses within a stage (add stage*STG_SZ)
    const u32 kA = gb + lane * 16;                    // K: local m = lane
    const u32 vA = gb + STG_K + lane * 80;            // V: c = lane
    const u32 vB = vA + 32 * 80;                      // V: c = 32 + lane
    // cp.async staging (group-local): K 4B/thread, V 2x16B/thread
    const u32 kDst = gb + gt * 4;
    const u32 vDst = gb + STG_K + (gt >> 1) * 80 + (gt & 1) * 32;
    const char* kSrc = gk + (size_t)(32 * h) * 16 + (gt >> 2) * 16 + (gt & 3) * 4;
    const char* vSrc = gv + ((size_t)(gt >> 1) * NN + 32 * h) * 2 + (gt & 1) * 32;

    // Prologue: stage chunks ck0..ck0+2 into stages 0..2 (this group's slices)
#pragma unroll
    for (int p = 0; p < 3; p++) {
        size_t off = (size_t)(ck0 + p) * 64;
        cp4(kDst + p * STG_SZ, kSrc + off * 16);
        cp16(vDst + p * STG_SZ, vSrc + off * 2);
        cp16(vDst + p * STG_SZ + 16, vSrc + off * 2 + 16);
        cp_commit();
    }

    // sQ is read cross-warp/cross-group: full barrier required before Q reads.
    __syncthreads();

    const u32 qa0 = *(const u32*)((const char*)sQ + r * 16 + t * 4);
    const u32 qa1 = *(const u32*)((const char*)sQ + (r + 8) * 16 + t * 4);

    float oC[8][4];
#pragma unroll
    for (int i = 0; i < 8; i++)
#pragma unroll
        for (int j = 0; j < 4; j++) oC[i][j] = 0.0f;
    float rs0 = 0.0f, rs1 = 0.0f;

    for (int ck = 0; ck < 32; ck++) {
        const u32 stOff = (u32)(ck & 3) * STG_SZ;

        // This group's chunk ck resident (2 groups slack); group-scope barrier.
        if (ck < 30) cp_wait2(); else cp_wait0();
        gbar(1 + h);

        // Stage chunk ck+3 into stage (ck+3)&3 (consumed at ck-1, bar above)
        if (ck < 29) {
            size_t off = (size_t)(ck0 + ck + 3) * 64;
            const u32 nb = ((ck + 3) & 3) * STG_SZ;
            cp4(kDst + nb, kSrc + off * 16);
            cp16(vDst + nb, vSrc + off * 2);
            cp16(vDst + nb + 16, vSrc + off * 2 + 16);
            cp_commit();
        }

        // K b-frags + all 4 S-mmas up front
        u32 kb[4];
        ldsm_x4(kb[0], kb[1], kb[2], kb[3], kA + stOff);
        float e[4][4];
#pragma unroll
        for (int j = 0; j < 4; j++) {
            e[j][0] = e[j][1] = e[j][2] = e[j][3] = 0.0f;
            mma_bf16_k8(e[j], qa0, qa1, kb[j]);
        }

        // ---- per-ks: V ldsm, ex2, O-mmas ----
#pragma unroll
        for (int ks = 0; ks < 2; ks++) {
            u32 bl[4][2], bh[4][2];
            {
                u32 base = stOff + 32 * ks;
                ldsm_x4(bl[0][0], bl[1][0], bl[2][0], bl[3][0], vA + base);
                ldsm_x4(bl[0][1], bl[1][1], bl[2][1], bl[3][1], vA + base + 16);
                ldsm_x4(bh[0][0], bh[1][0], bh[2][0], bh[3][0], vB + base);
                ldsm_x4(bh[0][1], bh[1][1], bh[2][1], bh[3][1], vB + base + 16);
            }
            float* e0 = e[2 * ks];
            float* e1 = e[2 * ks + 1];
            float p00 = ex2(e0[0]), p01 = ex2(e0[1]);
            float p02 = ex2(e0[2]), p03 = ex2(e0[3]);
            float p10 = ex2(e1[0]), p11 = ex2(e1[1]);
            float p12 = ex2(e1[2]), p13 = ex2(e1[3]);
            rs0 += p00 + p01 + p10 + p11;
            rs1 += p02 + p03 + p12 + p13;
            u32 a0 = packbf(p00, p01);
            u32 a1 = packbf(p02, p03);
            u32 a2 = packbf(p10, p11);
            u32 a3 = packbf(p12, p13);

#pragma unroll
            for (int cT = 0; cT < 4; cT++)
                mma_bf16_k16(oC[cT], a0, a1, a2, a3, bl[cT][0], bl[cT][1]);
#pragma unroll
            for (int cT = 0; cT < 4; cT++)
                mma_bf16_k16(oC[4 + cT], a0, a1, a2, a3, bh[cT][0], bh[cT][1]);
        }
    }

    // Rowsums
    rs0 += __shfl_xor_sync(0xffffffffu, rs0, 1);
    rs0 += __shfl_xor_sync(0xffffffffu, rs0, 2);
    rs1 += __shfl_xor_sync(0xffffffffu, rs1, 1);
    rs1 += __shfl_xor_sync(0xffffffffu, rs1, 2);
    if (t == 0) {
        sRS[r][h] = rs0;
        sRS[r + 8][h] = rs1;
    }
    __syncthreads();   // both groups done; rings dead; sO may be written

    // Cross-h O reduce into sO
    if (h == 0) {
#pragma unroll
        for (int cT = 0; cT < 8; cT++) {
            int c = 8 * cT + 2 * t;
            sO[r][c] = oC[cT][0];
            sO[r][c + 1] = oC[cT][1];
            sO[r + 8][c] = oC[cT][2];
            sO[r + 8][c + 1] = oC[cT][3];
        }
    }
    __syncthreads();
    if (h == 1) {
#pragma unroll
        for (int cT = 0; cT < 8; cT++) {
            int c = 8 * cT + 2 * t;
            sO[r][c] += oC[cT][0];
            sO[r][c + 1] += oC[cT][1];
            sO[r + 8][c] += oC[cT][2];
            sO[r + 8][c + 1] += oC[cT][3];
        }
    }
    __syncthreads();

    // Partial rowsum + partial bf16 O [s][b][c][n]
    if (tid < 64)
        g_prs[((size_t)s * BB + b) * NN + q0 + tid] = sRS[tid][0] + sRS[tid][1];
    {
        u32* po = (u32*)g_po + ((size_t)s * BB + b) * (CC * NN / 2);
#pragma unroll
        for (int k = 0; k < 8; k++) {
            int i = k * 256 + tid;
            int c = i >> 5, n2 = i & 31;
            po[(size_t)c * (NN / 2) + q0 / 2 + n2] = packbf(sO[2 * n2][c], sO[2 * n2 + 1][c]);
        }
    }

    // Ticket: last CTA of this (tile, b) performs the combine
    __threadfence();
    __syncthreads();
    if (tid == 0) sFlag = ((atomicAdd(&g_tk[b * 64 + blockIdx.x], 1) & (MSPLIT - 1)) == MSPLIT - 1);
    __syncthreads();

    if (sFlag) {
        __threadfence();
        if (tid < 64) {
            float rsum = 0.0f;
#pragma unroll
            for (int ss = 0; ss < MSPLIT; ss++)
                rsum += g_prs[((size_t)ss * BB + b) * NN + q0 + tid];
            sInv[tid] = gammap[0] / rsum;
        }
        __syncthreads();
#pragma unroll
        for (int k = 0; k < 8; k++) {
            int i = k * 256 + tid;
            int c = i >> 5, n2 = i & 31;
            size_t pi = (size_t)c * (NN / 2) + q0 / 2 + n2;
            float vx = 0.0f, vy = 0.0f;
#pragma unroll
            for (int ss = 0; ss < MSPLIT; ss++) {
                float2 v = unpackbf(((const u32*)g_po + ((size_t)ss * BB + b) * (CC * NN / 2))[pi]);
                vx += v.x;
                vy += v.y;
            }
            size_t gi = ((size_t)b * CC + c) * NN + q0 + 2 * n2;
            float2 xv = *(const float2*)&x[gi];
            float2 res;
            res.x = fmaf(vx, sInv[2 * n2], xv.x);
            res.y = fmaf(vy, sInv[2 * n2 + 1], xv.y);
            *(float2*)&out[gi] = res;
        }
    }
}

extern "C" void kernel_launch(void* const* d_in, const int* in_sizes, int n_in,
                              void* d_out, int out_size) {
    const float* x     = (const float*)d_in[0];
    const float* ctx   = (const float*)d_in[1];
    const float* Wq    = (const float*)d_in[2];
    const float* bq    = (const float*)d_in[3];
    const float* Wk    = (const float*)d_in[4];
    const float* bk    = (const float*)d_in[5];
    const float* Wv    = (const float*)d_in[6];
    const float* bv    = (const float*)d_in[7];
    const float* gamma = (const float*)d_in[8];
    float* out = (float*)d_out;

    proj_kernel<<<512, 256>>>(x, ctx, Wq, bq, Wk, bk, Wv, bv);
    attn_kernel<<<dim3(64, BB, MSPLIT), 256>>>(x, gamma, out);
}